// round 10
// baseline (speedup 1.0000x reference)
#include <cuda_runtime.h>
#include <cuda_fp16.h>
#include <cstdint>

#define B_DIM 1024
#define C_DIM 20
#define LC    5120
#define KC64  80           // LC / 64 K-chunks
#define TSCALE 256.0f
#define NT_TILES 3200      // prep_T tiles: 80(i) x 40(j)
#define NJT 40             // j-tiles of 128
#define SEG 8              // K-chunks per work item
#define NWORKERS 296       // 2 per SM

// ---------------------------------------------------------------------------
// Scratch: fp16 pairs, K-major, pair-permuted within each 64-chunk.
// g_Tp zero-initialized; masked tiles never written -> stay zero.
// ---------------------------------------------------------------------------
__device__ uint32_t g_Xp[(size_t)B_DIM * LC / 2];
__device__ uint32_t g_Tp[(size_t)LC * LC / 2];
__device__ unsigned int g_ctr;    // dynamic work-queue counter

__device__ __forceinline__ uint32_t smem_u32(const void* p) {
    uint32_t a;
    asm("{ .reg .u64 t; cvta.to.shared.u64 t, %1; cvt.u32.u64 %0, t; }"
        : "=r"(a) : "l"(p));
    return a;
}
__device__ __forceinline__ void cpa16(uint32_t dst, const char* gbase, uint32_t goff) {
    asm volatile("cp.async.cg.shared.global [%0], [%1], 16;"
                 :: "r"(dst), "l"(__cvta_generic_to_global(gbase + goff)));
}
#define CP_COMMIT() asm volatile("cp.async.commit_group;" ::: "memory")
#define CP_WAIT1()  asm volatile("cp.async.wait_group 1;" ::: "memory")

__device__ __forceinline__ void mma_f16(float c[4],
                                        uint32_t a0, uint32_t a1,
                                        uint32_t a2, uint32_t a3,
                                        uint32_t b0, uint32_t b1) {
    asm("mma.sync.aligned.m16n8k16.row.col.f32.f16.f16.f32 "
        "{%0,%1,%2,%3}, {%4,%5,%6,%7}, {%8,%9}, {%0,%1,%2,%3};"
        : "+f"(c[0]), "+f"(c[1]), "+f"(c[2]), "+f"(c[3])
        : "r"(a0), "r"(a1), "r"(a2), "r"(a3), "r"(b0), "r"(b1));
}

__device__ __forceinline__ int pair_word(int pl) {
    const int c  = pl >> 3;
    const int pc = pl & 7;
    return (pc & 3) * 8 + c * 2 + (pc >> 2);
}

// KPP for a j-tile (chunks of 64 in the triangle-skipped K range)
__device__ __forceinline__ int kpp_of(int jt) {
    const int Kmax = ((jt * 128 + 127) / C_DIM) * C_DIM;
    return (Kmax + 63) >> 6;
}

// ---------------------------------------------------------------------------
// Merged prep kernel (R9-proven) + queue-counter reset.
// ---------------------------------------------------------------------------
__global__ __launch_bounds__(256)
void prep_all(const float* __restrict__ X,
              const float* __restrict__ th0,
              const float* __restrict__ thlc,
              const float* __restrict__ T,
              float* __restrict__ out) {
    const int blk = blockIdx.x;
    const int t   = threadIdx.x;

    if (blk == 0 && t == 0) g_ctr = 0;   // reset work queue every launch

    if (blk < NT_TILES) {
        const int it = blk % (LC / 64);
        const int jt = blk / (LC / 64);
        const int i0 = it * 64;
        const int j0 = jt * 128;
        const int bound = ((j0 + 127) / C_DIM) * C_DIM;
        if (i0 >= bound) return;

        __shared__ float tile[64][132];
        {
            const int row = t >> 2;
            const int c16 = t & 3;
            const float* src = T + (size_t)(i0 + row) * LC + j0;
            #pragma unroll
            for (int rr = 0; rr < 8; rr++) {
                const int col4 = c16 + rr * 4;
                const float4 v = *reinterpret_cast<const float4*>(src + col4 * 4);
                *reinterpret_cast<float4*>(&tile[row][col4 * 4]) = v;
            }
        }
        __syncthreads();

        const int jl   = t >> 1;
        const int half = t & 1;
        const int wb   = half * 16;
        uint32_t buf[16];
        #pragma unroll
        for (int dw = 0; dw < 16; dw++) {
            const int w  = wb + dw;
            const int c  = (w & 7) >> 1;
            const int pc = ((w & 1) << 2) | (w >> 3);
            const int pl = (c << 3) | pc;
            const float v0 = tile[2 * pl][jl] * TSCALE;
            const float v1 = tile[2 * pl + 1][jl] * TSCALE;
            __half2 h = __floats2half2_rn(v0, v1);
            buf[dw] = *reinterpret_cast<uint32_t*>(&h);
        }
        uint32_t* dst = g_Tp + ((size_t)(j0 + jl) * KC64 + it) * 32 + wb;
        #pragma unroll
        for (int v = 0; v < 4; v++)
            *reinterpret_cast<uint4*>(dst + v * 4) =
                *reinterpret_cast<const uint4*>(&buf[v * 4]);
    } else {
        const int b = blk - NT_TILES;
        const float* xr = X + (size_t)b * LC;
        float s = 0.f;
        for (int k4 = t; k4 < LC / 4; k4 += 256) {
            const float4 xv = *reinterpret_cast<const float4*>(xr + k4 * 4);
            const float4 tv = *reinterpret_cast<const float4*>(thlc + k4 * 4);
            s += xv.x * tv.x + xv.y * tv.y + xv.z * tv.z + xv.w * tv.w;
            const int k  = k4 * 4;
            const int kc = k >> 6;
            const int pl = (k & 63) >> 1;
            uint32_t* base = g_Xp + ((size_t)b * KC64 + kc) * 32;
            __half2 h0 = __floats2half2_rn(xv.x, xv.y);
            __half2 h1 = __floats2half2_rn(xv.z, xv.w);
            base[pair_word(pl)]     = *reinterpret_cast<uint32_t*>(&h0);
            base[pair_word(pl + 1)] = *reinterpret_cast<uint32_t*>(&h1);
        }
        for (int o = 16; o > 0; o >>= 1) s += __shfl_xor_sync(0xffffffffu, s, o);
        __shared__ float red[8];
        if ((t & 31) == 0) red[t >> 5] = s;
        __syncthreads();
        if (t == 0) {
            float tt = 0.f;
            #pragma unroll
            for (int w = 0; w < 8; w++) tt += red[w];
            out[b] = th0[0] + tt;
        }
    }
}

// ---------------------------------------------------------------------------
// Persistent quad kernel with dynamic work queue.
// Work item = (j-tile jt, b-tile bt, K segment of up to SEG chunks of 64).
// Item order: heavy j-tiles first (jtq ascending -> jt = 39 - jtq).
// Per item: 3-stage cp.async pipeline, prefetch issued RIGHT AFTER the
// barrier (stage (ss+2)%3 is safe to write there), compute, epilogue dot
// of the partial accumulators with X, one atomicAdd per (b, item).
// ---------------------------------------------------------------------------
#define STAGE_BYTES 36864
#define BOFF        18432
#define SMEM_TOTAL  (3 * STAGE_BYTES + 128)
#define SMEM_G      (3 * STAGE_BYTES)

__global__ __launch_bounds__(256, 2)
void quad_tc_kernel(const float* __restrict__ X, float* __restrict__ out) {
    extern __shared__ char smem[];
    const uint32_t sb = smem_u32(smem);
    const int tid  = threadIdx.x;
    const int lane = tid & 31;
    const int w    = tid >> 5;
    const int g    = lane >> 2;
    const int q    = lane & 3;
    const int wm   = w & 1;
    const int wn   = w >> 1;

    const int rowL = tid >> 3;
    const int ch   = tid & 7;
    const uint32_t sAc = (uint32_t)(rowL * 144 + ch * 16);
    const char* gA = (const char*)g_Xp;
    const char* gB = (const char*)g_Tp;

    const uint32_t fA = (uint32_t)((wm * 64 + g) * 144 + q * 32);
    const uint32_t fB = (uint32_t)(BOFF + (wn * 32 + g) * 144 + q * 32);

    volatile unsigned int* gsh = (volatile unsigned int*)(smem + SMEM_G);

    for (;;) {
        // ---- fetch next work item (barrier also fences smem stage reuse) ----
        if (tid == 0) *gsh = atomicAdd(&g_ctr, 1u);
        __syncthreads();
        unsigned int item = *gsh;

        // decode item -> (jt, bt, seg)
        int jt = -1, rem = (int)item, nseg = 0, KPP = 0;
        #pragma unroll 1
        for (int jtq = 0; jtq < NJT; jtq++) {
            const int j = NJT - 1 - jtq;          // heavy first
            const int kp = kpp_of(j);
            const int ns = (kp + SEG - 1) / SEG;
            const int cnt = ns * 8;               // 8 b-tiles
            if (rem < cnt) { jt = j; nseg = ns; KPP = kp; break; }
            rem -= cnt;
        }
        if (jt < 0) break;                         // queue exhausted

        const int bt  = rem / nseg;
        const int seg = rem - bt * nseg;
        const int b0  = bt << 7;
        const int j0  = jt << 7;
        const int kc0 = seg * SEG;
        const int len = (KPP - kc0 < SEG) ? (KPP - kc0) : SEG;

        // per-item global offsets
        uint32_t gAc[4], gBc[4];
        #pragma unroll
        for (int i = 0; i < 4; i++) {
            const int row = rowL + i * 32;
            gAc[i] = (uint32_t)((b0 + row) * (KC64 * 128) + kc0 * 128 + ch * 16);
            gBc[i] = (uint32_t)((j0 + row) * (KC64 * 128) + kc0 * 128 + ch * 16);
        }

        float acc[4][4][4];
        #pragma unroll
        for (int mt = 0; mt < 4; mt++)
            #pragma unroll
            for (int nt = 0; nt < 4; nt++)
                #pragma unroll
                for (int c = 0; c < 4; c++) acc[mt][nt][c] = 0.f;

        // ---- prologue: stages 0,1 (second may be empty if len==1) ----
        {
            const uint32_t st0 = sb + sAc;
            #pragma unroll
            for (int i = 0; i < 4; i++) cpa16(st0 + i * (32 * 144), gA, gAc[i]);
            #pragma unroll
            for (int i = 0; i < 4; i++) cpa16(st0 + BOFF + i * (32 * 144), gB, gBc[i]);
            CP_COMMIT();
            if (len > 1) {
                const uint32_t st1 = sb + STAGE_BYTES + sAc;
                #pragma unroll
                for (int i = 0; i < 4; i++) cpa16(st1 + i * (32 * 144), gA, gAc[i] + 128);
                #pragma unroll
                for (int i = 0; i < 4; i++) cpa16(st1 + BOFF + i * (32 * 144), gB, gBc[i] + 128);
            }
            CP_COMMIT();
        }

        int ss = 0;
        for (int ks = 0; ks < len; ks++) {
            CP_WAIT1();
            __syncthreads();

            // prefetch chunk ks+2 into stage (ss+2)%3 — safe right after the
            // barrier (laggards from iter ks-1 have finished reading it).
            if (ks + 2 < len) {
                const int s2 = (ss + 2 >= 3) ? ss - 1 : ss + 2;
                const uint32_t st = sb + s2 * STAGE_BYTES + sAc;
                const uint32_t ko = (uint32_t)(ks + 2) * 128;
                #pragma unroll
                for (int i = 0; i < 4; i++) cpa16(st + i * (32 * 144), gA, gAc[i] + ko);
                #pragma unroll
                for (int i = 0; i < 4; i++) cpa16(st + BOFF + i * (32 * 144), gB, gBc[i] + ko);
            }
            CP_COMMIT();

            const char* aB = smem + ss * STAGE_BYTES;
            #pragma unroll
            for (int sp = 0; sp < 2; sp++) {
                uint4 bf[4];
                #pragma unroll
                for (int nt = 0; nt < 4; nt++)
                    bf[nt] = *reinterpret_cast<const uint4*>(aB + fB + nt * (8 * 144) + sp * 16);
                #pragma unroll
                for (int mt = 0; mt < 4; mt++) {
                    const char* ap = aB + fA + mt * (16 * 144) + sp * 16;
                    uint4 al = *reinterpret_cast<const uint4*>(ap);
                    uint4 ah = *reinterpret_cast<const uint4*>(ap + 8 * 144);
                    #pragma unroll
                    for (int t2 = 0; t2 < 2; t2++) {
                        const uint32_t a0 = t2 ? al.z : al.x;
                        const uint32_t a2 = t2 ? al.w : al.y;
                        const uint32_t a1 = t2 ? ah.z : ah.x;
                        const uint32_t a3 = t2 ? ah.w : ah.y;
                        #pragma unroll
                        for (int nt = 0; nt < 4; nt++) {
                            const uint32_t b0r = t2 ? bf[nt].z : bf[nt].x;
                            const uint32_t b1r = t2 ? bf[nt].w : bf[nt].y;
                            mma_f16(acc[mt][nt], a0, a1, a2, a3, b0r, b1r);
                        }
                    }
                }
            }
            ss = (ss + 1 >= 3) ? 0 : ss + 1;
        }

        // ---- epilogue: out[b] += (1/TSCALE) * sum_j Ypartial[b,j] * X[b,j]
        #pragma unroll
        for (int mt = 0; mt < 4; mt++) {
            #pragma unroll
            for (int hh = 0; hh < 2; hh++) {
                const int b = b0 + wm * 64 + mt * 16 + g + 8 * hh;
                const float* xr = X + (size_t)b * LC + j0 + wn * 32;
                float s = 0.f;
                #pragma unroll
                for (int nt = 0; nt < 4; nt++) {
                    float2 xv = *reinterpret_cast<const float2*>(xr + nt * 8 + 2 * q);
                    s += acc[mt][nt][2 * hh] * xv.x + acc[mt][nt][2 * hh + 1] * xv.y;
                }
                s += __shfl_xor_sync(0xffffffffu, s, 1);
                s += __shfl_xor_sync(0xffffffffu, s, 2);
                if (q == 0) atomicAdd(&out[b], s * (1.0f / TSCALE));
            }
        }
    }
}

// ---------------------------------------------------------------------------
// Inputs: x_lc (B,L,C) f32 | theta_0 (1,) | theta_lc (1,L,C) |
//         theta_lclc (1,L,C,L,C) pre-masked f32 | mask (unused)
// Output: (B,1) f32
// ---------------------------------------------------------------------------
extern "C" void kernel_launch(void* const* d_in, const int* in_sizes, int n_in,
                              void* d_out, int out_size) {
    const float* x      = (const float*)d_in[0];
    const float* th0    = (const float*)d_in[1];
    const float* thlc   = (const float*)d_in[2];
    const float* thlclc = (const float*)d_in[3];
    float* out = (float*)d_out;

    cudaFuncSetAttribute(quad_tc_kernel,
                         cudaFuncAttributeMaxDynamicSharedMemorySize, SMEM_TOTAL);

    prep_all<<<NT_TILES + B_DIM, 256>>>(x, th0, thlc, thlclc, out);
    quad_tc_kernel<<<NWORKERS, 256, SMEM_TOTAL>>>(x, out);
}

// round 11
// speedup vs baseline: 1.1265x; 1.1265x over previous
#include <cuda_runtime.h>
#include <cuda_fp16.h>
#include <cstdint>

#define B_DIM 1024
#define C_DIM 20
#define LC    5120
#define KC64  80           // LC / 64 K-chunks
#define TSCALE 256.0f
#define NT_TILES 3200      // prep_T tiles: 80(i) x 40(j)

// ---------------------------------------------------------------------------
// Scratch: fp16 pairs, K-major, pair-permuted within each 64-chunk.
// word(pl): c=pl>>3, pc=pl&7 -> w = (pc&3)*8 + c*2 + (pc>>2)
// g_Tp zero-initialized; masked tiles never written -> stay zero.
// ---------------------------------------------------------------------------
__device__ uint32_t g_Xp[(size_t)B_DIM * LC / 2];
__device__ uint32_t g_Tp[(size_t)LC * LC / 2];

__device__ __forceinline__ uint32_t smem_u32(const void* p) {
    uint32_t a;
    asm("{ .reg .u64 t; cvta.to.shared.u64 t, %1; cvt.u32.u64 %0, t; }"
        : "=r"(a) : "l"(p));
    return a;
}
__device__ __forceinline__ void cpa16(uint32_t dst, const char* gbase, uint32_t goff) {
    asm volatile("cp.async.cg.shared.global [%0], [%1], 16;"
                 :: "r"(dst), "l"(__cvta_generic_to_global(gbase + goff)));
}
#define CP_COMMIT() asm volatile("cp.async.commit_group;" ::: "memory")
#define CP_WAIT1()  asm volatile("cp.async.wait_group 1;" ::: "memory")

__device__ __forceinline__ void mma_f16(float c[4],
                                        uint32_t a0, uint32_t a1,
                                        uint32_t a2, uint32_t a3,
                                        uint32_t b0, uint32_t b1) {
    asm("mma.sync.aligned.m16n8k16.row.col.f32.f16.f16.f32 "
        "{%0,%1,%2,%3}, {%4,%5,%6,%7}, {%8,%9}, {%0,%1,%2,%3};"
        : "+f"(c[0]), "+f"(c[1]), "+f"(c[2]), "+f"(c[3])
        : "r"(a0), "r"(a1), "r"(a2), "r"(a3), "r"(b0), "r"(b1));
}

__device__ __forceinline__ int pair_word(int pl) {
    const int c  = pl >> 3;
    const int pc = pl & 7;
    return (pc & 3) * 8 + c * 2 + (pc >> 2);
}

// ---------------------------------------------------------------------------
// Merged prep kernel (R9-proven).
// ---------------------------------------------------------------------------
__global__ __launch_bounds__(256)
void prep_all(const float* __restrict__ X,
              const float* __restrict__ th0,
              const float* __restrict__ thlc,
              const float* __restrict__ T,
              float* __restrict__ out) {
    const int blk = blockIdx.x;
    const int t   = threadIdx.x;

    if (blk < NT_TILES) {
        const int it = blk % (LC / 64);
        const int jt = blk / (LC / 64);
        const int i0 = it * 64;
        const int j0 = jt * 128;
        const int bound = ((j0 + 127) / C_DIM) * C_DIM;
        if (i0 >= bound) return;

        __shared__ float tile[64][132];
        {
            const int row = t >> 2;
            const int c16 = t & 3;
            const float* src = T + (size_t)(i0 + row) * LC + j0;
            #pragma unroll
            for (int rr = 0; rr < 8; rr++) {
                const int col4 = c16 + rr * 4;
                const float4 v = *reinterpret_cast<const float4*>(src + col4 * 4);
                *reinterpret_cast<float4*>(&tile[row][col4 * 4]) = v;
            }
        }
        __syncthreads();

        const int jl   = t >> 1;
        const int half = t & 1;
        const int wb   = half * 16;
        uint32_t buf[16];
        #pragma unroll
        for (int dw = 0; dw < 16; dw++) {
            const int w  = wb + dw;
            const int c  = (w & 7) >> 1;
            const int pc = ((w & 1) << 2) | (w >> 3);
            const int pl = (c << 3) | pc;
            const float v0 = tile[2 * pl][jl] * TSCALE;
            const float v1 = tile[2 * pl + 1][jl] * TSCALE;
            __half2 h = __floats2half2_rn(v0, v1);
            buf[dw] = *reinterpret_cast<uint32_t*>(&h);
        }
        uint32_t* dst = g_Tp + ((size_t)(j0 + jl) * KC64 + it) * 32 + wb;
        #pragma unroll
        for (int v = 0; v < 4; v++)
            *reinterpret_cast<uint4*>(dst + v * 4) =
                *reinterpret_cast<const uint4*>(&buf[v * 4]);
    } else {
        const int b = blk - NT_TILES;
        const float* xr = X + (size_t)b * LC;
        float s = 0.f;
        for (int k4 = t; k4 < LC / 4; k4 += 256) {
            const float4 xv = *reinterpret_cast<const float4*>(xr + k4 * 4);
            const float4 tv = *reinterpret_cast<const float4*>(thlc + k4 * 4);
            s += xv.x * tv.x + xv.y * tv.y + xv.z * tv.z + xv.w * tv.w;
            const int k  = k4 * 4;
            const int kc = k >> 6;
            const int pl = (k & 63) >> 1;
            uint32_t* base = g_Xp + ((size_t)b * KC64 + kc) * 32;
            __half2 h0 = __floats2half2_rn(xv.x, xv.y);
            __half2 h1 = __floats2half2_rn(xv.z, xv.w);
            base[pair_word(pl)]     = *reinterpret_cast<uint32_t*>(&h0);
            base[pair_word(pl + 1)] = *reinterpret_cast<uint32_t*>(&h1);
        }
        for (int o = 16; o > 0; o >>= 1) s += __shfl_xor_sync(0xffffffffu, s, o);
        __shared__ float red[8];
        if ((t & 31) == 0) red[t >> 5] = s;
        __syncthreads();
        if (t == 0) {
            float tt = 0.f;
            #pragma unroll
            for (int w = 0; w < 8; w++) tt += red[w];
            out[b] = th0[0] + tt;
        }
    }
}

// ---------------------------------------------------------------------------
// quad kernel (R9 static schedule + EARLY prefetch + incremented offsets):
// out[b] += (1/TSCALE) * x_b^T T' x_b
// CTA 128(b) x 128(j) x BK=64 fp16, 256 threads, 3-stage cp.async pipeline.
// Prefetch for chunk ks+2 is issued IMMEDIATELY after the barrier — the
// barrier is exactly the fence proving stage (ss+2)%3 has no readers left.
// ---------------------------------------------------------------------------
#define STAGE_BYTES 36864
#define BOFF        18432
#define SMEM_TOTAL  (3 * STAGE_BYTES)

__global__ __launch_bounds__(256, 2)
void quad_tc_kernel(const float* __restrict__ X, float* __restrict__ out) {
    extern __shared__ char smem[];
    const uint32_t sb = smem_u32(smem);
    const int tid  = threadIdx.x;
    const int lane = tid & 31;
    const int w    = tid >> 5;
    const int g    = lane >> 2;
    const int q    = lane & 3;
    const int wm   = w & 1;
    const int wn   = w >> 1;

    // work-balanced static tile map (R9-proven)
    const int bid = blockIdx.x;
    int r;
    if (bid < 148)      r = bid * 2;
    else if (bid < 296) r = 591 - 2 * bid;
    else                r = bid;
    const int jt = 39 - (r >> 3);
    const int b0 = (r & 7) << 7;
    const int j0 = jt << 7;

    const int Kmax = ((j0 + 127) / C_DIM) * C_DIM;
    const int KPP  = (Kmax + 63) >> 6;

    const int rowL = tid >> 3;
    const int ch   = tid & 7;
    // incremented source offsets: advance by 128 B per chunk consumed
    uint32_t gAo[4], gBo[4];
    #pragma unroll
    for (int i = 0; i < 4; i++) {
        const int row = rowL + i * 32;
        gAo[i] = (uint32_t)((b0 + row) * (KC64 * 128) + ch * 16) + 256; // chunk 2 base
        gBo[i] = (uint32_t)((j0 + row) * (KC64 * 128) + ch * 16) + 256;
    }
    const uint32_t sAc = (uint32_t)(rowL * 144 + ch * 16);
    const char* gA = (const char*)g_Xp;
    const char* gB = (const char*)g_Tp;

    float acc[4][4][4];
    #pragma unroll
    for (int mt = 0; mt < 4; mt++)
        #pragma unroll
        for (int nt = 0; nt < 4; nt++)
            #pragma unroll
            for (int c = 0; c < 4; c++) acc[mt][nt][c] = 0.f;

    // prologue: chunks 0,1 into stages 0,1 (KPP >= 2 always)
    #pragma unroll
    for (int s = 0; s < 2; s++) {
        const uint32_t st = sb + s * STAGE_BYTES + sAc;
        const int ko = s * 128 - 256;
        #pragma unroll
        for (int i = 0; i < 4; i++) cpa16(st + i * (32 * 144), gA, gAo[i] + ko);
        #pragma unroll
        for (int i = 0; i < 4; i++) cpa16(st + BOFF + i * (32 * 144), gB, gBo[i] + ko);
        CP_COMMIT();
    }

    const uint32_t fA = (uint32_t)((wm * 64 + g) * 144 + q * 32);
    const uint32_t fB = (uint32_t)(BOFF + (wn * 32 + g) * 144 + q * 32);

    int ss = 0;
    for (int ks = 0; ks < KPP; ks++) {
        CP_WAIT1();
        __syncthreads();

        // EARLY prefetch: chunk ks+2 -> stage (ss+2)%3, issued before compute
        if (ks + 2 < KPP) {
            const int s2 = (ss + 2 >= 3) ? ss - 1 : ss + 2;
            const uint32_t st = sb + s2 * STAGE_BYTES + sAc;
            #pragma unroll
            for (int i = 0; i < 4; i++) cpa16(st + i * (32 * 144), gA, gAo[i]);
            #pragma unroll
            for (int i = 0; i < 4; i++) cpa16(st + BOFF + i * (32 * 144), gB, gBo[i]);
        }
        CP_COMMIT();
        #pragma unroll
        for (int i = 0; i < 4; i++) { gAo[i] += 128; gBo[i] += 128; }

        const char* aB = smem + ss * STAGE_BYTES;
        #pragma unroll
        for (int sp = 0; sp < 2; sp++) {
            uint4 bf[4];
            #pragma unroll
            for (int nt = 0; nt < 4; nt++)
                bf[nt] = *reinterpret_cast<const uint4*>(aB + fB + nt * (8 * 144) + sp * 16);
            #pragma unroll
            for (int mt = 0; mt < 4; mt++) {
                const char* ap = aB + fA + mt * (16 * 144) + sp * 16;
                uint4 al = *reinterpret_cast<const uint4*>(ap);
                uint4 ah = *reinterpret_cast<const uint4*>(ap + 8 * 144);
                #pragma unroll
                for (int t = 0; t < 2; t++) {
                    const uint32_t a0 = t ? al.z : al.x;
                    const uint32_t a2 = t ? al.w : al.y;
                    const uint32_t a1 = t ? ah.z : ah.x;
                    const uint32_t a3 = t ? ah.w : ah.y;
                    #pragma unroll
                    for (int nt = 0; nt < 4; nt++) {
                        const uint32_t b0r = t ? bf[nt].z : bf[nt].x;
                        const uint32_t b1r = t ? bf[nt].w : bf[nt].y;
                        mma_f16(acc[mt][nt], a0, a1, a2, a3, b0r, b1r);
                    }
                }
            }
        }
        ss = (ss + 1 >= 3) ? 0 : ss + 1;
    }

    // fused epilogue
    #pragma unroll
    for (int mt = 0; mt < 4; mt++) {
        #pragma unroll
        for (int hh = 0; hh < 2; hh++) {
            const int b = b0 + wm * 64 + mt * 16 + g + 8 * hh;
            const float* xr = X + (size_t)b * LC + j0 + wn * 32;
            float s = 0.f;
            #pragma unroll
            for (int nt = 0; nt < 4; nt++) {
                float2 xv = *reinterpret_cast<const float2*>(xr + nt * 8 + 2 * q);
                s += acc[mt][nt][2 * hh] * xv.x + acc[mt][nt][2 * hh + 1] * xv.y;
            }
            s += __shfl_xor_sync(0xffffffffu, s, 1);
            s += __shfl_xor_sync(0xffffffffu, s, 2);
            if (q == 0) atomicAdd(&out[b], s * (1.0f / TSCALE));
        }
    }
}

// ---------------------------------------------------------------------------
// Inputs: x_lc (B,L,C) f32 | theta_0 (1,) | theta_lc (1,L,C) |
//         theta_lclc (1,L,C,L,C) pre-masked f32 | mask (unused)
// Output: (B,1) f32
// ---------------------------------------------------------------------------
extern "C" void kernel_launch(void* const* d_in, const int* in_sizes, int n_in,
                              void* d_out, int out_size) {
    const float* x      = (const float*)d_in[0];
    const float* th0    = (const float*)d_in[1];
    const float* thlc   = (const float*)d_in[2];
    const float* thlclc = (const float*)d_in[3];
    float* out = (float*)d_out;

    cudaFuncSetAttribute(quad_tc_kernel,
                         cudaFuncAttributeMaxDynamicSharedMemorySize, SMEM_TOTAL);

    prep_all<<<NT_TILES + B_DIM, 256>>>(x, th0, thlc, thlclc, out);
    quad_tc_kernel<<<320, 256, SMEM_TOTAL>>>(x, out);
}

// round 12
// speedup vs baseline: 1.1301x; 1.0032x over previous
#include <cuda_runtime.h>
#include <cuda_fp16.h>
#include <cstdint>

#define B_DIM 1024
#define C_DIM 20
#define LC    5120
#define KC64  80           // LC / 64 K-chunks
#define TSCALE 256.0f
#define NT_TILES 3200      // prep_T tiles: 80(i) x 40(j)
#define NITEMS 480         // quad work items (see decode)

// ---------------------------------------------------------------------------
// Scratch: fp16 pairs, K-major, pair-permuted within each 64-chunk.
// g_Tp zero-initialized; masked tiles never written -> stay zero.
// ---------------------------------------------------------------------------
__device__ uint32_t g_Xp[(size_t)B_DIM * LC / 2];
__device__ uint32_t g_Tp[(size_t)LC * LC / 2];

__device__ __forceinline__ uint32_t smem_u32(const void* p) {
    uint32_t a;
    asm("{ .reg .u64 t; cvta.to.shared.u64 t, %1; cvt.u32.u64 %0, t; }"
        : "=r"(a) : "l"(p));
    return a;
}
__device__ __forceinline__ void cpa16(uint32_t dst, const char* gbase, uint32_t goff) {
    asm volatile("cp.async.cg.shared.global [%0], [%1], 16;"
                 :: "r"(dst), "l"(__cvta_generic_to_global(gbase + goff)));
}
#define CP_COMMIT() asm volatile("cp.async.commit_group;" ::: "memory")
#define CP_WAIT1()  asm volatile("cp.async.wait_group 1;" ::: "memory")

__device__ __forceinline__ void mma_f16(float c[4],
                                        uint32_t a0, uint32_t a1,
                                        uint32_t a2, uint32_t a3,
                                        uint32_t b0, uint32_t b1) {
    asm("mma.sync.aligned.m16n8k16.row.col.f32.f16.f16.f32 "
        "{%0,%1,%2,%3}, {%4,%5,%6,%7}, {%8,%9}, {%0,%1,%2,%3};"
        : "+f"(c[0]), "+f"(c[1]), "+f"(c[2]), "+f"(c[3])
        : "r"(a0), "r"(a1), "r"(a2), "r"(a3), "r"(b0), "r"(b1));
}

__device__ __forceinline__ int pair_word(int pl) {
    const int c  = pl >> 3;
    const int pc = pl & 7;
    return (pc & 3) * 8 + c * 2 + (pc >> 2);
}

// K-chunks (of 64) in the triangle-skipped K range for j-tile jt
__device__ __forceinline__ int kpp_of(int jt) {
    const int Kmax = ((jt * 128 + 127) / C_DIM) * C_DIM;
    return (Kmax + 63) >> 6;
}

// ---------------------------------------------------------------------------
// Merged prep kernel (R9-proven, unchanged).
// ---------------------------------------------------------------------------
__global__ __launch_bounds__(256)
void prep_all(const float* __restrict__ X,
              const float* __restrict__ th0,
              const float* __restrict__ thlc,
              const float* __restrict__ T,
              float* __restrict__ out) {
    const int blk = blockIdx.x;
    const int t   = threadIdx.x;

    if (blk < NT_TILES) {
        const int it = blk % (LC / 64);
        const int jt = blk / (LC / 64);
        const int i0 = it * 64;
        const int j0 = jt * 128;
        const int bound = ((j0 + 127) / C_DIM) * C_DIM;
        if (i0 >= bound) return;

        __shared__ float tile[64][132];
        {
            const int row = t >> 2;
            const int c16 = t & 3;
            const float* src = T + (size_t)(i0 + row) * LC + j0;
            #pragma unroll
            for (int rr = 0; rr < 8; rr++) {
                const int col4 = c16 + rr * 4;
                const float4 v = *reinterpret_cast<const float4*>(src + col4 * 4);
                *reinterpret_cast<float4*>(&tile[row][col4 * 4]) = v;
            }
        }
        __syncthreads();

        const int jl   = t >> 1;
        const int half = t & 1;
        const int wb   = half * 16;
        uint32_t buf[16];
        #pragma unroll
        for (int dw = 0; dw < 16; dw++) {
            const int w  = wb + dw;
            const int c  = (w & 7) >> 1;
            const int pc = ((w & 1) << 2) | (w >> 3);
            const int pl = (c << 3) | pc;
            const float v0 = tile[2 * pl][jl] * TSCALE;
            const float v1 = tile[2 * pl + 1][jl] * TSCALE;
            __half2 h = __floats2half2_rn(v0, v1);
            buf[dw] = *reinterpret_cast<uint32_t*>(&h);
        }
        uint32_t* dst = g_Tp + ((size_t)(j0 + jl) * KC64 + it) * 32 + wb;
        #pragma unroll
        for (int v = 0; v < 4; v++)
            *reinterpret_cast<uint4*>(dst + v * 4) =
                *reinterpret_cast<const uint4*>(&buf[v * 4]);
    } else {
        const int b = blk - NT_TILES;
        const float* xr = X + (size_t)b * LC;
        float s = 0.f;
        for (int k4 = t; k4 < LC / 4; k4 += 256) {
            const float4 xv = *reinterpret_cast<const float4*>(xr + k4 * 4);
            const float4 tv = *reinterpret_cast<const float4*>(thlc + k4 * 4);
            s += xv.x * tv.x + xv.y * tv.y + xv.z * tv.z + xv.w * tv.w;
            const int k  = k4 * 4;
            const int kc = k >> 6;
            const int pl = (k & 63) >> 1;
            uint32_t* base = g_Xp + ((size_t)b * KC64 + kc) * 32;
            __half2 h0 = __floats2half2_rn(xv.x, xv.y);
            __half2 h1 = __floats2half2_rn(xv.z, xv.w);
            base[pair_word(pl)]     = *reinterpret_cast<uint32_t*>(&h0);
            base[pair_word(pl + 1)] = *reinterpret_cast<uint32_t*>(&h1);
        }
        for (int o = 16; o > 0; o >>= 1) s += __shfl_xor_sync(0xffffffffu, s, o);
        __shared__ float red[8];
        if ((t & 31) == 0) red[t >> 5] = s;
        __syncthreads();
        if (t == 0) {
            float tt = 0.f;
            #pragma unroll
            for (int w = 0; w < 8; w++) tt += red[w];
            out[b] = th0[0] + tt;
        }
    }
}

// ---------------------------------------------------------------------------
// quad kernel — R9 loop body, LPT-ordered split work items.
// Item = (jt, bt, [kc0, kc0+len) K-chunk range).
//   jt >= 20: tile split into half0 [0, ceil(KPP/2)) and half1 [ceil, KPP)
//   jt <  20: full tile.
// Items enumerated in descending length via a 2-sequence merge; blockIdx
// order == launch order -> LPT packing across SM slots.
// ---------------------------------------------------------------------------
#define STAGE_BYTES 36864
#define BOFF        18432
#define SMEM_TOTAL  (3 * STAGE_BYTES)

__global__ __launch_bounds__(256, 2)
void quad_tc_kernel(const float* __restrict__ X, float* __restrict__ out) {
    extern __shared__ char smem[];
    const uint32_t sb = smem_u32(smem);
    const int tid  = threadIdx.x;
    const int lane = tid & 31;
    const int w    = tid >> 5;
    const int g    = lane >> 2;
    const int q    = lane & 3;
    const int wm   = w & 1;
    const int wn   = w >> 1;

    // ---- decode blockIdx -> (jt, bt, kc0, len) via desc-length merge ----
    int jt = 0, bt = 0, kc0 = 0, len = 0;
    {
        const int idx = (int)blockIdx.x;
        int is = 0, ifu = 0, base = 0;
        #pragma unroll 1
        for (int step = 0; step < 60; step++) {
            int lenS = -1, kppS = 0, jtS = 0;
            if (is < 40) {
                jtS  = 39 - (is >> 1);
                kppS = kpp_of(jtS);
                lenS = (is & 1) ? (kppS >> 1) : (kppS - (kppS >> 1));
            }
            int lenF = -1, jtF = 0;
            if (ifu < 20) { jtF = 19 - ifu; lenF = kpp_of(jtF); }
            const bool takeS = (is < 40) && (ifu >= 20 || lenS >= lenF);
            if (idx < base + 8) {
                bt = idx - base;
                if (takeS) {
                    jt  = jtS;
                    len = lenS;
                    kc0 = (is & 1) ? (kppS - (kppS >> 1)) : 0;
                } else {
                    jt  = jtF;
                    len = lenF;
                    kc0 = 0;
                }
                break;
            }
            base += 8;
            if (takeS) is++; else ifu++;
        }
    }

    const int b0 = bt << 7;
    const int j0 = jt << 7;

    const int rowL = tid >> 3;
    const int ch   = tid & 7;
    uint32_t gAc[4], gBc[4];
    #pragma unroll
    for (int i = 0; i < 4; i++) {
        const int row = rowL + i * 32;
        gAc[i] = (uint32_t)((b0 + row) * (KC64 * 128) + kc0 * 128 + ch * 16);
        gBc[i] = (uint32_t)((j0 + row) * (KC64 * 128) + kc0 * 128 + ch * 16);
    }
    const uint32_t sAc = (uint32_t)(rowL * 144 + ch * 16);
    const char* gA = (const char*)g_Xp;
    const char* gB = (const char*)g_Tp;

    float acc[4][4][4];
    #pragma unroll
    for (int mt = 0; mt < 4; mt++)
        #pragma unroll
        for (int nt = 0; nt < 4; nt++)
            #pragma unroll
            for (int c = 0; c < 4; c++) acc[mt][nt][c] = 0.f;

    // prologue: chunks kc0, kc0+1 (len >= 2 always: min item is full jt0 = 2)
    #pragma unroll
    for (int s = 0; s < 2; s++) {
        const uint32_t st = sb + s * STAGE_BYTES + sAc;
        const uint32_t ko = (uint32_t)s * 128;
        #pragma unroll
        for (int i = 0; i < 4; i++) cpa16(st + i * (32 * 144), gA, gAc[i] + ko);
        #pragma unroll
        for (int i = 0; i < 4; i++) cpa16(st + BOFF + i * (32 * 144), gB, gBc[i] + ko);
        CP_COMMIT();
    }

    const uint32_t fA = (uint32_t)((wm * 64 + g) * 144 + q * 32);
    const uint32_t fB = (uint32_t)(BOFF + (wn * 32 + g) * 144 + q * 32);

    int ss = 0;
    for (int ks = 0; ks < len; ks++) {
        CP_WAIT1();
        __syncthreads();

        const char* aB = smem + ss * STAGE_BYTES;
        #pragma unroll
        for (int sp = 0; sp < 2; sp++) {
            uint4 bf[4];
            #pragma unroll
            for (int nt = 0; nt < 4; nt++)
                bf[nt] = *reinterpret_cast<const uint4*>(aB + fB + nt * (8 * 144) + sp * 16);
            #pragma unroll
            for (int mt = 0; mt < 4; mt++) {
                const char* ap = aB + fA + mt * (16 * 144) + sp * 16;
                uint4 al = *reinterpret_cast<const uint4*>(ap);
                uint4 ah = *reinterpret_cast<const uint4*>(ap + 8 * 144);
                #pragma unroll
                for (int t = 0; t < 2; t++) {
                    const uint32_t a0 = t ? al.z : al.x;
                    const uint32_t a2 = t ? al.w : al.y;
                    const uint32_t a1 = t ? ah.z : ah.x;
                    const uint32_t a3 = t ? ah.w : ah.y;
                    #pragma unroll
                    for (int nt = 0; nt < 4; nt++) {
                        const uint32_t b0r = t ? bf[nt].z : bf[nt].x;
                        const uint32_t b1r = t ? bf[nt].w : bf[nt].y;
                        mma_f16(acc[mt][nt], a0, a1, a2, a3, b0r, b1r);
                    }
                }
            }
        }
        __syncthreads();
        if (ks + 2 < len) {
            const int s2 = (ss + 2 >= 3) ? ss - 1 : ss + 2;
            const uint32_t st = sb + s2 * STAGE_BYTES + sAc;
            const uint32_t ko = (uint32_t)(ks + 2) * 128;
            #pragma unroll
            for (int i = 0; i < 4; i++) cpa16(st + i * (32 * 144), gA, gAc[i] + ko);
            #pragma unroll
            for (int i = 0; i < 4; i++) cpa16(st + BOFF + i * (32 * 144), gB, gBc[i] + ko);
        }
        CP_COMMIT();
        ss = (ss + 1 >= 3) ? 0 : ss + 1;
    }

    // fused epilogue: out[b] += (1/TSCALE) * sum_j Ypartial[b,j] * X[b,j]
    #pragma unroll
    for (int mt = 0; mt < 4; mt++) {
        #pragma unroll
        for (int hh = 0; hh < 2; hh++) {
            const int b = b0 + wm * 64 + mt * 16 + g + 8 * hh;
            const float* xr = X + (size_t)b * LC + j0 + wn * 32;
            float s = 0.f;
            #pragma unroll
            for (int nt = 0; nt < 4; nt++) {
                float2 xv = *reinterpret_cast<const float2*>(xr + nt * 8 + 2 * q);
                s += acc[mt][nt][2 * hh] * xv.x + acc[mt][nt][2 * hh + 1] * xv.y;
            }
            s += __shfl_xor_sync(0xffffffffu, s, 1);
            s += __shfl_xor_sync(0xffffffffu, s, 2);
            if (q == 0) atomicAdd(&out[b], s * (1.0f / TSCALE));
        }
    }
}

// ---------------------------------------------------------------------------
// Inputs: x_lc (B,L,C) f32 | theta_0 (1,) | theta_lc (1,L,C) |
//         theta_lclc (1,L,C,L,C) pre-masked f32 | mask (unused)
// Output: (B,1) f32
// ---------------------------------------------------------------------------
extern "C" void kernel_launch(void* const* d_in, const int* in_sizes, int n_in,
                              void* d_out, int out_size) {
    const float* x      = (const float*)d_in[0];
    const float* th0    = (const float*)d_in[1];
    const float* thlc   = (const float*)d_in[2];
    const float* thlclc = (const float*)d_in[3];
    float* out = (float*)d_out;

    cudaFuncSetAttribute(quad_tc_kernel,
                         cudaFuncAttributeMaxDynamicSharedMemorySize, SMEM_TOTAL);

    prep_all<<<NT_TILES + B_DIM, 256>>>(x, th0, thlc, thlclc, out);
    quad_tc_kernel<<<NITEMS, 256, SMEM_TOTAL>>>(x, out);
}

// round 13
// speedup vs baseline: 1.2580x; 1.1131x over previous
#include <cuda_runtime.h>
#include <cuda_fp16.h>
#include <cstdint>

#define B_DIM 1024
#define C_DIM 20
#define LC    5120
#define KC64  80           // LC / 64 K-chunks
#define TSCALE 256.0f
#define NT_TILES 3200      // prep_T tiles: 80(i) x 40(j)
#define NITEMS 480         // quad work items

// ---------------------------------------------------------------------------
// Scratch: fp16 pairs, K-major, pair-permuted within each 64-chunk.
// g_Tp zero-initialized; masked tiles never written -> stay zero.
// g_items: LPT-ordered work schedule {jt, bt, kc0, len}, written by prep_all.
// ---------------------------------------------------------------------------
__device__ uint32_t g_Xp[(size_t)B_DIM * LC / 2];
__device__ uint32_t g_Tp[(size_t)LC * LC / 2];
__device__ int4     g_items[NITEMS];

__device__ __forceinline__ uint32_t smem_u32(const void* p) {
    uint32_t a;
    asm("{ .reg .u64 t; cvta.to.shared.u64 t, %1; cvt.u32.u64 %0, t; }"
        : "=r"(a) : "l"(p));
    return a;
}
__device__ __forceinline__ void cpa16(uint32_t dst, const char* gbase, uint32_t goff) {
    asm volatile("cp.async.cg.shared.global [%0], [%1], 16;"
                 :: "r"(dst), "l"(__cvta_generic_to_global(gbase + goff)));
}
#define CP_COMMIT() asm volatile("cp.async.commit_group;" ::: "memory")
#define CP_WAIT1()  asm volatile("cp.async.wait_group 1;" ::: "memory")

__device__ __forceinline__ void mma_f16(float c[4],
                                        uint32_t a0, uint32_t a1,
                                        uint32_t a2, uint32_t a3,
                                        uint32_t b0, uint32_t b1) {
    asm("mma.sync.aligned.m16n8k16.row.col.f32.f16.f16.f32 "
        "{%0,%1,%2,%3}, {%4,%5,%6,%7}, {%8,%9}, {%0,%1,%2,%3};"
        : "+f"(c[0]), "+f"(c[1]), "+f"(c[2]), "+f"(c[3])
        : "r"(a0), "r"(a1), "r"(a2), "r"(a3), "r"(b0), "r"(b1));
}

__device__ __forceinline__ int pair_word(int pl) {
    const int c  = pl >> 3;
    const int pc = pl & 7;
    return (pc & 3) * 8 + c * 2 + (pc >> 2);
}

__device__ __forceinline__ int kpp_of(int jt) {
    const int Kmax = ((jt * 128 + 127) / C_DIM) * C_DIM;
    return (Kmax + 63) >> 6;
}

// ---------------------------------------------------------------------------
// Merged prep kernel: prep_T tiles, prep_X + init out, and (block 0 of the
// prep_X range) the quad work-item schedule.
// ---------------------------------------------------------------------------
__global__ __launch_bounds__(256)
void prep_all(const float* __restrict__ X,
              const float* __restrict__ th0,
              const float* __restrict__ thlc,
              const float* __restrict__ T,
              float* __restrict__ out) {
    const int blk = blockIdx.x;
    const int t   = threadIdx.x;

    if (blk < NT_TILES) {
        const int it = blk % (LC / 64);
        const int jt = blk / (LC / 64);
        const int i0 = it * 64;
        const int j0 = jt * 128;
        const int bound = ((j0 + 127) / C_DIM) * C_DIM;
        if (i0 >= bound) return;

        __shared__ float tile[64][132];
        {
            const int row = t >> 2;
            const int c16 = t & 3;
            const float* src = T + (size_t)(i0 + row) * LC + j0;
            #pragma unroll
            for (int rr = 0; rr < 8; rr++) {
                const int col4 = c16 + rr * 4;
                const float4 v = *reinterpret_cast<const float4*>(src + col4 * 4);
                *reinterpret_cast<float4*>(&tile[row][col4 * 4]) = v;
            }
        }
        __syncthreads();

        const int jl   = t >> 1;
        const int half = t & 1;
        const int wb   = half * 16;
        uint32_t buf[16];
        #pragma unroll
        for (int dw = 0; dw < 16; dw++) {
            const int w  = wb + dw;
            const int c  = (w & 7) >> 1;
            const int pc = ((w & 1) << 2) | (w >> 3);
            const int pl = (c << 3) | pc;
            const float v0 = tile[2 * pl][jl] * TSCALE;
            const float v1 = tile[2 * pl + 1][jl] * TSCALE;
            __half2 h = __floats2half2_rn(v0, v1);
            buf[dw] = *reinterpret_cast<uint32_t*>(&h);
        }
        uint32_t* dst = g_Tp + ((size_t)(j0 + jl) * KC64 + it) * 32 + wb;
        #pragma unroll
        for (int v = 0; v < 4; v++)
            *reinterpret_cast<uint4*>(dst + v * 4) =
                *reinterpret_cast<const uint4*>(&buf[v * 4]);
    } else {
        const int b = blk - NT_TILES;

        // block for b==0 also writes the quad schedule (2 items per thread)
        if (b == 0) {
            for (int idx = t; idx < NITEMS; idx += 256) {
                int is = 0, ifu = 0, base = 0;
                int jt = 0, bt = 0, kc0 = 0, len = 0;
                for (int step = 0; step < 60; step++) {
                    int lenS = -1, kppS = 0, jtS = 0;
                    if (is < 40) {
                        jtS  = 39 - (is >> 1);
                        kppS = kpp_of(jtS);
                        lenS = (is & 1) ? (kppS >> 1) : (kppS - (kppS >> 1));
                    }
                    int lenF = -1, jtF = 0;
                    if (ifu < 20) { jtF = 19 - ifu; lenF = kpp_of(jtF); }
                    const bool takeS = (is < 40) && (ifu >= 20 || lenS >= lenF);
                    if (idx < base + 8) {
                        bt = idx - base;
                        if (takeS) {
                            jt  = jtS;
                            len = lenS;
                            kc0 = (is & 1) ? (kppS - (kppS >> 1)) : 0;
                        } else {
                            jt = jtF; len = lenF; kc0 = 0;
                        }
                        break;
                    }
                    base += 8;
                    if (takeS) is++; else ifu++;
                }
                g_items[idx] = make_int4(jt, bt, kc0, len);
            }
        }

        const float* xr = X + (size_t)b * LC;
        float s = 0.f;
        for (int k4 = t; k4 < LC / 4; k4 += 256) {
            const float4 xv = *reinterpret_cast<const float4*>(xr + k4 * 4);
            const float4 tv = *reinterpret_cast<const float4*>(thlc + k4 * 4);
            s += xv.x * tv.x + xv.y * tv.y + xv.z * tv.z + xv.w * tv.w;
            const int k  = k4 * 4;
            const int kc = k >> 6;
            const int pl = (k & 63) >> 1;
            uint32_t* base = g_Xp + ((size_t)b * KC64 + kc) * 32;
            __half2 h0 = __floats2half2_rn(xv.x, xv.y);
            __half2 h1 = __floats2half2_rn(xv.z, xv.w);
            base[pair_word(pl)]     = *reinterpret_cast<uint32_t*>(&h0);
            base[pair_word(pl + 1)] = *reinterpret_cast<uint32_t*>(&h1);
        }
        for (int o = 16; o > 0; o >>= 1) s += __shfl_xor_sync(0xffffffffu, s, o);
        __shared__ float red[8];
        if ((t & 31) == 0) red[t >> 5] = s;
        __syncthreads();
        if (t == 0) {
            float tt = 0.f;
            #pragma unroll
            for (int w = 0; w < 8; w++) tt += red[w];
            out[b] = th0[0] + tt;
        }
    }
}

// ---------------------------------------------------------------------------
// quad kernel — R9 loop body (ONE barrier per chunk), LPT-ordered split
// items read from g_items. Item = (jt, bt, [kc0, kc0+len)).
// ---------------------------------------------------------------------------
#define STAGE_BYTES 36864
#define BOFF        18432
#define SMEM_TOTAL  (3 * STAGE_BYTES)

__global__ __launch_bounds__(256, 2)
void quad_tc_kernel(const float* __restrict__ X, float* __restrict__ out) {
    extern __shared__ char smem[];
    const uint32_t sb = smem_u32(smem);
    const int tid  = threadIdx.x;
    const int lane = tid & 31;
    const int w    = tid >> 5;
    const int g    = lane >> 2;
    const int q    = lane & 3;
    const int wm   = w & 1;
    const int wn   = w >> 1;

    const int4 item = g_items[blockIdx.x];
    const int jt  = item.x;
    const int bt  = item.y;
    const int kc0 = item.z;
    const int len = item.w;

    const int b0 = bt << 7;
    const int j0 = jt << 7;

    const int rowL = tid >> 3;
    const int ch   = tid & 7;
    uint32_t gAc[4], gBc[4];
    #pragma unroll
    for (int i = 0; i < 4; i++) {
        const int row = rowL + i * 32;
        gAc[i] = (uint32_t)((b0 + row) * (KC64 * 128) + kc0 * 128 + ch * 16);
        gBc[i] = (uint32_t)((j0 + row) * (KC64 * 128) + kc0 * 128 + ch * 16);
    }
    const uint32_t sAc = (uint32_t)(rowL * 144 + ch * 16);
    const char* gA = (const char*)g_Xp;
    const char* gB = (const char*)g_Tp;

    float acc[4][4][4];
    #pragma unroll
    for (int mt = 0; mt < 4; mt++)
        #pragma unroll
        for (int nt = 0; nt < 4; nt++)
            #pragma unroll
            for (int c = 0; c < 4; c++) acc[mt][nt][c] = 0.f;

    // prologue: chunks kc0, kc0+1 (len >= 2 always)
    #pragma unroll
    for (int s = 0; s < 2; s++) {
        const uint32_t st = sb + s * STAGE_BYTES + sAc;
        const uint32_t ko = (uint32_t)s * 128;
        #pragma unroll
        for (int i = 0; i < 4; i++) cpa16(st + i * (32 * 144), gA, gAc[i] + ko);
        #pragma unroll
        for (int i = 0; i < 4; i++) cpa16(st + BOFF + i * (32 * 144), gB, gBc[i] + ko);
        CP_COMMIT();
    }

    const uint32_t fA = (uint32_t)((wm * 64 + g) * 144 + q * 32);
    const uint32_t fB = (uint32_t)(BOFF + (wn * 32 + g) * 144 + q * 32);

    int ss = 0;
    for (int ks = 0; ks < len; ks++) {
        CP_WAIT1();
        __syncthreads();

        const char* aB = smem + ss * STAGE_BYTES;
        #pragma unroll
        for (int sp = 0; sp < 2; sp++) {
            uint4 bf[4];
            #pragma unroll
            for (int nt = 0; nt < 4; nt++)
                bf[nt] = *reinterpret_cast<const uint4*>(aB + fB + nt * (8 * 144) + sp * 16);
            #pragma unroll
            for (int mt = 0; mt < 4; mt++) {
                const char* ap = aB + fA + mt * (16 * 144) + sp * 16;
                uint4 al = *reinterpret_cast<const uint4*>(ap);
                uint4 ah = *reinterpret_cast<const uint4*>(ap + 8 * 144);
                #pragma unroll
                for (int t = 0; t < 2; t++) {
                    const uint32_t a0 = t ? al.z : al.x;
                    const uint32_t a2 = t ? al.w : al.y;
                    const uint32_t a1 = t ? ah.z : ah.x;
                    const uint32_t a3 = t ? ah.w : ah.y;
                    #pragma unroll
                    for (int nt = 0; nt < 4; nt++) {
                        const uint32_t b0r = t ? bf[nt].z : bf[nt].x;
                        const uint32_t b1r = t ? bf[nt].w : bf[nt].y;
                        mma_f16(acc[mt][nt], a0, a1, a2, a3, b0r, b1r);
                    }
                }
            }
        }
        // prefetch chunk ks+2 into stage (ss+2)%3 — safe without a second
        // barrier: any reader of that stage finished iteration ks-1 before
        // the top-of-loop barrier of iteration ks (R9-validated).
        if (ks + 2 < len) {
            const int s2 = (ss + 2 >= 3) ? ss - 1 : ss + 2;
            const uint32_t st = sb + s2 * STAGE_BYTES + sAc;
            const uint32_t ko = (uint32_t)(ks + 2) * 128;
            #pragma unroll
            for (int i = 0; i < 4; i++) cpa16(st + i * (32 * 144), gA, gAc[i] + ko);
            #pragma unroll
            for (int i = 0; i < 4; i++) cpa16(st + BOFF + i * (32 * 144), gB, gBc[i] + ko);
        }
        CP_COMMIT();
        ss = (ss + 1 >= 3) ? 0 : ss + 1;
    }

    // fused epilogue: out[b] += (1/TSCALE) * sum_j Ypartial[b,j] * X[b,j]
    #pragma unroll
    for (int mt = 0; mt < 4; mt++) {
        #pragma unroll
        for (int hh = 0; hh < 2; hh++) {
            const int b = b0 + wm * 64 + mt * 16 + g + 8 * hh;
            const float* xr = X + (size_t)b * LC + j0 + wn * 32;
            float s = 0.f;
            #pragma unroll
            for (int nt = 0; nt < 4; nt++) {
                float2 xv = *reinterpret_cast<const float2*>(xr + nt * 8 + 2 * q);
                s += acc[mt][nt][2 * hh] * xv.x + acc[mt][nt][2 * hh + 1] * xv.y;
            }
            s += __shfl_xor_sync(0xffffffffu, s, 1);
            s += __shfl_xor_sync(0xffffffffu, s, 2);
            if (q == 0) atomicAdd(&out[b], s * (1.0f / TSCALE));
        }
    }
}

// ---------------------------------------------------------------------------
// Inputs: x_lc (B,L,C) f32 | theta_0 (1,) | theta_lc (1,L,C) |
//         theta_lclc (1,L,C,L,C) pre-masked f32 | mask (unused)
// Output: (B,1) f32
// ---------------------------------------------------------------------------
extern "C" void kernel_launch(void* const* d_in, const int* in_sizes, int n_in,
                              void* d_out, int out_size) {
    const float* x      = (const float*)d_in[0];
    const float* th0    = (const float*)d_in[1];
    const float* thlc   = (const float*)d_in[2];
    const float* thlclc = (const float*)d_in[3];
    float* out = (float*)d_out;

    cudaFuncSetAttribute(quad_tc_kernel,
                         cudaFuncAttributeMaxDynamicSharedMemorySize, SMEM_TOTAL);

    prep_all<<<NT_TILES + B_DIM, 256>>>(x, th0, thlc, thlclc, out);
    quad_tc_kernel<<<NITEMS, 256, SMEM_TOTAL>>>(x, out);
}